// round 4
// baseline (speedup 1.0000x reference)
#include <cuda_runtime.h>

#define C        128
#define NB       16
#define GROUPS   32
#define CPG      4
#define EPS      1e-5f
#define RWARPS   4736            // 592 blocks x 8 warps: exactly one wave at 4 blk/SM

// Allocation-free scratch (harness forbids cudaMalloc anywhere).
__device__ float  g_sum[NB][C];
__device__ float  g_sq [NB][C];
__device__ int    g_seg[NB + 1];       // segment start offsets (sorted batch_id)
__device__ float2 g_ms [NB][GROUPS];   // (mean, inv_std) per (batch, group)

// Fused: zero accumulators + binary-search the 17 segment boundaries.
__global__ void init_kernel(const int* __restrict__ bid, int n) {
    int i = threadIdx.x;
    float* s = &g_sum[0][0];
    float* q = &g_sq[0][0];
    for (int j = i; j < NB * C; j += blockDim.x) { s[j] = 0.f; q[j] = 0.f; }
    if (i <= NB) {
        int lo = 0, hi = n;             // lower_bound(bid, i)
        while (lo < hi) {
            int mid = (lo + hi) >> 1;
            if (bid[mid] < i) lo = mid + 1; else hi = mid;
        }
        g_seg[i] = lo;
    }
}

__device__ __forceinline__ void flush_acc(int b, int lane,
                                          const float4& s, const float4& q) {
    int c0 = lane * 4;
    atomicAdd(&g_sum[b][c0 + 0], s.x);
    atomicAdd(&g_sum[b][c0 + 1], s.y);
    atomicAdd(&g_sum[b][c0 + 2], s.z);
    atomicAdd(&g_sum[b][c0 + 3], s.w);
    atomicAdd(&g_sq [b][c0 + 0], q.x);
    atomicAdd(&g_sq [b][c0 + 1], q.y);
    atomicAdd(&g_sq [b][c0 + 2], q.z);
    atomicAdd(&g_sq [b][c0 + 3], q.w);
}

// One wave: each warp owns a contiguous run of rpw rows; lane l owns ch [4l,4l+4).
// Explicit 8-deep load batching forces front-batched LDG.128 (high MLP).
__global__ void __launch_bounds__(256, 4)
reduce_kernel(const float4* __restrict__ data,
              const int*    __restrict__ bid,
              int n, int rpw) {
    int lane = threadIdx.x & 31;
    int warp = (blockIdx.x * blockDim.x + threadIdx.x) >> 5;
    int r0 = warp * rpw;
    if (r0 >= n) return;
    int r1 = min(n, r0 + rpw);

    int b0 = bid[r0];
    int b1 = bid[r1 - 1];

    float4 s = make_float4(0.f, 0.f, 0.f, 0.f);
    float4 q = make_float4(0.f, 0.f, 0.f, 0.f);

    if (b0 == b1) {
        // Fast path: whole run in one segment.
        int r = r0;
        for (; r + 8 <= r1; r += 8) {
            float4 v[8];
#pragma unroll
            for (int u = 0; u < 8; ++u)
                v[u] = __ldcs(&data[(r + u) * 32 + lane]);
#pragma unroll
            for (int u = 0; u < 8; ++u) {
                s.x += v[u].x; s.y += v[u].y; s.z += v[u].z; s.w += v[u].w;
                q.x += v[u].x * v[u].x; q.y += v[u].y * v[u].y;
                q.z += v[u].z * v[u].z; q.w += v[u].w * v[u].w;
            }
        }
        for (; r < r1; ++r) {
            float4 v = __ldcs(&data[r * 32 + lane]);
            s.x += v.x; s.y += v.y; s.z += v.z; s.w += v.w;
            q.x += v.x * v.x; q.y += v.y * v.y; q.z += v.z * v.z; q.w += v.w * v.w;
        }
        flush_acc(b0, lane, s, q);
    } else {
        // Slow path (<= NB-1 warps total): per-row segment tracking.
        int cur = b0;
        for (int r = r0; r < r1; ++r) {
            int b = bid[r];
            if (b != cur) {
                flush_acc(cur, lane, s, q);
                s = make_float4(0.f, 0.f, 0.f, 0.f);
                q = make_float4(0.f, 0.f, 0.f, 0.f);
                cur = b;
            }
            float4 v = __ldcs(&data[r * 32 + lane]);
            s.x += v.x; s.y += v.y; s.z += v.z; s.w += v.w;
            q.x += v.x * v.x; q.y += v.y * v.y; q.z += v.z * v.z; q.w += v.w * v.w;
        }
        flush_acc(cur, lane, s, q);
    }
}

// Per-(batch, group) mean and inv_std, matching reference math:
//   inv_count = 1/(cnt*CPG + EPS)
//   m_g   = (sum of 4 per-channel sums) * inv_count
//   var_g = (sq_g - 2*m_g*s_g + CPG*cnt*m_g^2) * inv_count
__global__ void stats_kernel() {
    int idx = threadIdx.x;
    if (idx >= NB * GROUPS) return;
    int b = idx >> 5;
    int g = idx & 31;
    float cnt  = (float)(g_seg[b + 1] - g_seg[b]);
    float invc = 1.f / (cnt * (float)CPG + EPS);
    float s = 0.f, sq = 0.f;
#pragma unroll
    for (int k = 0; k < CPG; ++k) {
        s  += g_sum[b][g * 4 + k];
        sq += g_sq [b][g * 4 + k];
    }
    float m   = s * invc;
    float var = (sq - 2.f * m * s + (float)CPG * cnt * m * m) * invc;
    g_ms[b][g] = make_float2(m, rsqrtf(var + EPS));
}

// Lane l covers channels [4l,4l+4) == exactly group l (CPG=4, GROUPS=32).
__global__ void apply_kernel(const float4* __restrict__ data,
                             const float4* __restrict__ w4,
                             const float4* __restrict__ bias4,
                             const int*    __restrict__ bid,
                             float4*       __restrict__ out,
                             int n) {
    int lane   = threadIdx.x & 31;
    int warp   = (blockIdx.x * blockDim.x + threadIdx.x) >> 5;
    int nwarps = (gridDim.x * blockDim.x) >> 5;
    float4 w  = w4[lane];
    float4 bb = bias4[lane];

    for (int r = warp; r < n; r += nwarps) {
        int b = __ldg(&bid[r]);               // warp-uniform
        float2 ms = g_ms[b][lane];            // 4KB table, L1/L2-resident
        float4 v  = __ldcs(&data[r * 32 + lane]);
        float4 o;
        o.x = (v.x - ms.x) * ms.y * w.x + bb.x;
        o.y = (v.y - ms.x) * ms.y * w.y + bb.y;
        o.z = (v.z - ms.x) * ms.y * w.z + bb.z;
        o.w = (v.w - ms.x) * ms.y * w.w + bb.w;
        __stcs(&out[r * 32 + lane], o);
    }
}

extern "C" void kernel_launch(void* const* d_in, const int* in_sizes, int n_in,
                              void* d_out, int out_size) {
    const float* data = (const float*)d_in[0];
    const float* w    = (const float*)d_in[1];
    const float* bias = (const float*)d_in[2];
    const int*   bid  = (const int*)d_in[3];
    int n = in_sizes[3];                      // rows (batch_id length)

    init_kernel<<<1, 256>>>(bid, n);

    int rpw = (n + RWARPS - 1) / RWARPS;      // rows per warp, one wave
    reduce_kernel<<<RWARPS / 8, 256>>>((const float4*)data, bid, n, rpw);

    stats_kernel<<<1, 512>>>();

    apply_kernel<<<2048, 256>>>((const float4*)data, (const float4*)w,
                                (const float4*)bias, bid,
                                (float4*)d_out, n);
}

// round 5
// speedup vs baseline: 1.1430x; 1.1430x over previous
#include <cuda_runtime.h>

#define C        128
#define NB       16
#define GROUPS   32
#define CPG      4
#define EPS      1e-5f
#define RPW      128            // rows per warp in reduce (smaller chunks, multi-wave balance)

// Allocation-free scratch (harness forbids cudaMalloc anywhere).
__device__ float  g_sum[NB][C];
__device__ float  g_sq [NB][C];
__device__ int    g_seg[NB + 1];       // segment start offsets (sorted batch_id)
__device__ float2 g_ms [NB][GROUPS];   // (mean, inv_std) per (batch, group)

// Fused: zero accumulators + binary-search the 17 segment boundaries.
__global__ void init_kernel(const int* __restrict__ bid, int n) {
    int i = threadIdx.x;
    float* s = &g_sum[0][0];
    float* q = &g_sq[0][0];
    for (int j = i; j < NB * C; j += blockDim.x) { s[j] = 0.f; q[j] = 0.f; }
    if (i <= NB) {
        int lo = 0, hi = n;             // lower_bound(bid, i)
        while (lo < hi) {
            int mid = (lo + hi) >> 1;
            if (bid[mid] < i) lo = mid + 1; else hi = mid;
        }
        g_seg[i] = lo;
    }
}

__device__ __forceinline__ void flush_acc(int b, int lane,
                                          const float4& s, const float4& q) {
    int c0 = lane * 4;
    atomicAdd(&g_sum[b][c0 + 0], s.x);
    atomicAdd(&g_sum[b][c0 + 1], s.y);
    atomicAdd(&g_sum[b][c0 + 2], s.z);
    atomicAdd(&g_sum[b][c0 + 3], s.w);
    atomicAdd(&g_sq [b][c0 + 0], q.x);
    atomicAdd(&g_sq [b][c0 + 1], q.y);
    atomicAdd(&g_sq [b][c0 + 2], q.z);
    atomicAdd(&g_sq [b][c0 + 3], q.w);
}

// Each warp reduces RPW contiguous rows; lane l owns channels [4l, 4l+4).
// R2-proven structure: inline accumulate, unroll 8, no launch bounds.
__global__ void reduce_kernel(const float4* __restrict__ data,
                              const int*    __restrict__ bid,
                              int n) {
    int lane = threadIdx.x & 31;
    int warp = (blockIdx.x * blockDim.x + threadIdx.x) >> 5;
    int r0 = warp * RPW;
    if (r0 >= n) return;
    int r1 = min(n, r0 + RPW);

    int b0 = bid[r0];
    int b1 = bid[r1 - 1];

    float4 s = make_float4(0.f, 0.f, 0.f, 0.f);
    float4 q = make_float4(0.f, 0.f, 0.f, 0.f);

    if (b0 == b1) {
        // Fast path: whole run in one segment — branch-free, bid-free.
#pragma unroll 8
        for (int r = r0; r < r1; ++r) {
            float4 v = __ldcs(&data[r * 32 + lane]);
            s.x += v.x; s.y += v.y; s.z += v.z; s.w += v.w;
            q.x += v.x * v.x; q.y += v.y * v.y; q.z += v.z * v.z; q.w += v.w * v.w;
        }
        flush_acc(b0, lane, s, q);
    } else {
        // Slow path (<= NB-1 warps total): per-row segment tracking.
        int cur = b0;
        for (int r = r0; r < r1; ++r) {
            int b = bid[r];
            if (b != cur) {
                flush_acc(cur, lane, s, q);
                s = make_float4(0.f, 0.f, 0.f, 0.f);
                q = make_float4(0.f, 0.f, 0.f, 0.f);
                cur = b;
            }
            float4 v = __ldcs(&data[r * 32 + lane]);
            s.x += v.x; s.y += v.y; s.z += v.z; s.w += v.w;
            q.x += v.x * v.x; q.y += v.y * v.y; q.z += v.z * v.z; q.w += v.w * v.w;
        }
        flush_acc(cur, lane, s, q);
    }
}

// Per-(batch, group) mean and inv_std, matching reference math:
//   inv_count = 1/(cnt*CPG + EPS)
//   m_g   = (sum of 4 per-channel sums) * inv_count
//   var_g = (sq_g - 2*m_g*s_g + CPG*cnt*m_g^2) * inv_count
__global__ void stats_kernel() {
    int idx = threadIdx.x;
    if (idx >= NB * GROUPS) return;
    int b = idx >> 5;
    int g = idx & 31;
    float cnt  = (float)(g_seg[b + 1] - g_seg[b]);
    float invc = 1.f / (cnt * (float)CPG + EPS);
    float s = 0.f, sq = 0.f;
#pragma unroll
    for (int k = 0; k < CPG; ++k) {
        s  += g_sum[b][g * 4 + k];
        sq += g_sq [b][g * 4 + k];
    }
    float m   = s * invc;
    float var = (sq - 2.f * m * s + (float)CPG * cnt * m * m) * invc;
    g_ms[b][g] = make_float2(m, rsqrtf(var + EPS));
}

// Lane l covers channels [4l,4l+4) == exactly group l (CPG=4, GROUPS=32).
// Unchanged from the 571us best: this kernel runs at ~83% of HBM already.
__global__ void apply_kernel(const float4* __restrict__ data,
                             const float4* __restrict__ w4,
                             const float4* __restrict__ bias4,
                             const int*    __restrict__ bid,
                             float4*       __restrict__ out,
                             int n) {
    int lane   = threadIdx.x & 31;
    int warp   = (blockIdx.x * blockDim.x + threadIdx.x) >> 5;
    int nwarps = (gridDim.x * blockDim.x) >> 5;
    float4 w  = w4[lane];
    float4 bb = bias4[lane];

    for (int r = warp; r < n; r += nwarps) {
        int b = bid[r];                       // warp-uniform
        float2 ms = g_ms[b][lane];            // 4KB table, L1/L2-resident
        float4 v  = __ldcs(&data[r * 32 + lane]);
        float4 o;
        o.x = (v.x - ms.x) * ms.y * w.x + bb.x;
        o.y = (v.y - ms.x) * ms.y * w.y + bb.y;
        o.z = (v.z - ms.x) * ms.y * w.z + bb.z;
        o.w = (v.w - ms.x) * ms.y * w.w + bb.w;
        __stcs(&out[r * 32 + lane], o);
    }
}

extern "C" void kernel_launch(void* const* d_in, const int* in_sizes, int n_in,
                              void* d_out, int out_size) {
    const float* data = (const float*)d_in[0];
    const float* w    = (const float*)d_in[1];
    const float* bias = (const float*)d_in[2];
    const int*   bid  = (const int*)d_in[3];
    int n = in_sizes[3];                      // rows (batch_id length)

    init_kernel<<<1, 256>>>(bid, n);

    int warps  = (n + RPW - 1) / RPW;
    int blocks = (warps + 7) / 8;             // 8 warps / block
    reduce_kernel<<<blocks, 256>>>((const float4*)data, bid, n);

    stats_kernel<<<1, 512>>>();

    apply_kernel<<<2048, 256>>>((const float4*)data, (const float4*)w,
                                (const float4*)bias, bid,
                                (float4*)d_out, n);
}